// round 1
// baseline (speedup 1.0000x reference)
#include <cuda_runtime.h>

#define BN   32
#define SEQ  577
#define CH   768
#define NH   12
#define DH   64
#define MROWS (BN*SEQ)      /* 18464 */
#define QKV_N (3*CH)        /* 2304  */

// Scratch (allocation-free rule: __device__ globals)
__device__ float g_q[BN*NH*SEQ*DH];   // [B,H,N,DH], pre-scaled by DH^-0.5
__device__ float g_k[BN*NH*SEQ*DH];
__device__ float g_v[BN*NH*SEQ*DH];
__device__ float g_o[BN*SEQ*CH];      // attention output, [B,N,C]

// ---------------------------------------------------------------------------
// SGEMM: C[M,Nw] = A[M,K] * W[Nw,K]^T + bias.  BM=BN=128, BK=16, 256 thr, 8x8.
// MODE 0: A = x, W = qkv_w -> scatter into g_q/g_k/g_v (q scaled).
// MODE 1: A = g_o, W = proj_w -> write d_out.
// ---------------------------------------------------------------------------
template<int MODE>
__global__ __launch_bounds__(256) void sgemm_kernel(
    const float* __restrict__ A, const float* __restrict__ W,
    const float* __restrict__ bias, float* __restrict__ out)
{
    __shared__ float As[16][132];
    __shared__ float Bs[16][132];
    const int tid  = threadIdx.x;
    const int brow = blockIdx.y * 128;
    const int bcol = blockIdx.x * 128;
    const int lrow = tid >> 2;          // 0..63
    const int lk4  = (tid & 3) << 2;    // 0,4,8,12
    const int trow = (tid >> 4) << 3;   // 0..120 step 8
    const int tc4  = (tid & 15) << 2;   // 0..60 step 4 (cols tc4..+3 and 64+tc4..+3)

    const float* Ap = (MODE == 0) ? A : g_o;

    float acc[8][8];
    #pragma unroll
    for (int i = 0; i < 8; ++i)
        #pragma unroll
        for (int j = 0; j < 8; ++j) acc[i][j] = 0.f;

    for (int kt = 0; kt < CH; kt += 16) {
        #pragma unroll
        for (int p = 0; p < 2; ++p) {
            int r  = lrow + p*64;
            int gr = brow + r; if (gr >= MROWS) gr = MROWS-1;
            float4 v = *(const float4*)(Ap + gr*CH + kt + lk4);
            As[lk4+0][r] = v.x; As[lk4+1][r] = v.y;
            As[lk4+2][r] = v.z; As[lk4+3][r] = v.w;
        }
        #pragma unroll
        for (int p = 0; p < 2; ++p) {
            int r = lrow + p*64;
            float4 v = *(const float4*)(W + (bcol + r)*CH + kt + lk4);
            Bs[lk4+0][r] = v.x; Bs[lk4+1][r] = v.y;
            Bs[lk4+2][r] = v.z; Bs[lk4+3][r] = v.w;
        }
        __syncthreads();
        #pragma unroll
        for (int k = 0; k < 16; ++k) {
            float a[8], b[8];
            *(float4*)&a[0] = *(const float4*)&As[k][trow];
            *(float4*)&a[4] = *(const float4*)&As[k][trow+4];
            *(float4*)&b[0] = *(const float4*)&Bs[k][tc4];
            *(float4*)&b[4] = *(const float4*)&Bs[k][64+tc4];
            #pragma unroll
            for (int i = 0; i < 8; ++i)
                #pragma unroll
                for (int j = 0; j < 8; ++j)
                    acc[i][j] = fmaf(a[i], b[j], acc[i][j]);
        }
        __syncthreads();
    }

    if (MODE == 0) {
        int rOK[8]; int base[8];
        #pragma unroll
        for (int i = 0; i < 8; ++i) {
            int gr = brow + trow + i;
            rOK[i] = (gr < MROWS);
            int bb = gr / SEQ; int n = gr - bb*SEQ;
            base[i] = (bb*NH*SEQ + n) * DH;
        }
        #pragma unroll
        for (int j = 0; j < 8; ++j) {
            int gc = bcol + ((j < 4) ? (tc4 + j) : (60 + tc4 + j));
            float bv = bias[gc];
            int s = gc / CH; int rem = gc - s*CH;
            int h = rem >> 6; int d = rem & 63;
            float scl = (s == 0) ? 0.125f : 1.0f;   // DH^-0.5 folded into q
            float* dst = (s == 0) ? g_q : (s == 1) ? g_k : g_v;
            int off = h*(SEQ*DH) + d;
            #pragma unroll
            for (int i = 0; i < 8; ++i)
                if (rOK[i]) dst[base[i] + off] = (acc[i][j] + bv) * scl;
        }
    } else {
        #pragma unroll
        for (int i = 0; i < 8; ++i) {
            int gr = brow + trow + i;
            if (gr < MROWS) {
                float4 o0, o1;
                o0.x = acc[i][0] + bias[bcol + tc4 + 0];
                o0.y = acc[i][1] + bias[bcol + tc4 + 1];
                o0.z = acc[i][2] + bias[bcol + tc4 + 2];
                o0.w = acc[i][3] + bias[bcol + tc4 + 3];
                o1.x = acc[i][4] + bias[bcol + 64 + tc4 + 0];
                o1.y = acc[i][5] + bias[bcol + 64 + tc4 + 1];
                o1.z = acc[i][6] + bias[bcol + 64 + tc4 + 2];
                o1.w = acc[i][7] + bias[bcol + 64 + tc4 + 3];
                *(float4*)(out + gr*CH + bcol + tc4)      = o0;
                *(float4*)(out + gr*CH + bcol + 64 + tc4) = o1;
            }
        }
    }
}

// ---------------------------------------------------------------------------
// Flash attention: one (b, h, 64-query tile) per 64-thread block.
// 8x8 microtile, 64-key tiles, online softmax. XOR-swizzled smem.
// sigmoid->logit straight-through == identity forward => plain softmax.
// ---------------------------------------------------------------------------
__device__ __forceinline__ int swz(int r, int c4) {
    return (r << 4) + (c4 ^ ((r >> 2) & 7));
}

__global__ __launch_bounds__(64) void attn_kernel()
{
    __shared__ float4 sQ[1024];   // 16 KB each; sP aliases sK; total 48 KB
    __shared__ float4 sK[1024];
    __shared__ float4 sV[1024];

    const int tid = threadIdx.x;
    const int q0  = blockIdx.x << 6;
    const int h   = blockIdx.y, b = blockIdx.z;
    const int bh  = b*NH + h;
    const float* Qb = g_q + bh*SEQ*DH;
    const float* Kb = g_k + bh*SEQ*DH;
    const float* Vb = g_v + bh*SEQ*DH;
    const int trow = (tid >> 3) << 3;   // query rows trow..trow+7
    const int tc   = tid & 7;           // key/d cols: tc*4..+3 and 32+tc*4..+3

    #pragma unroll
    for (int p = 0; p < 16; ++p) {
        int f = tid + (p << 6);
        int r = f >> 4, c4 = f & 15;
        int gr = q0 + r; if (gr > SEQ-1) gr = SEQ-1;
        sQ[swz(r, c4)] = *(const float4*)(Qb + gr*DH + (c4 << 2));
    }

    float o[8][8];
    float mrow[8], lrow[8];
    #pragma unroll
    for (int i = 0; i < 8; ++i) {
        mrow[i] = -1e30f; lrow[i] = 0.f;
        #pragma unroll
        for (int j = 0; j < 8; ++j) o[i][j] = 0.f;
    }

    int kidx[8];
    #pragma unroll
    for (int j = 0; j < 8; ++j) kidx[j] = (j < 4) ? (tc*4 + j) : (28 + tc*4 + j);

    for (int kt = 0; kt < 10; ++kt) {
        const int k0 = kt << 6;
        __syncthreads();                       // prior PV reads of sP/sV done
        #pragma unroll
        for (int p = 0; p < 16; ++p) {
            int f = tid + (p << 6);
            int r = f >> 4, c4 = f & 15;
            int gr = k0 + r; if (gr > SEQ-1) gr = SEQ-1;
            sK[swz(r, c4)] = *(const float4*)(Kb + gr*DH + (c4 << 2));
            sV[swz(r, c4)] = *(const float4*)(Vb + gr*DH + (c4 << 2));
        }
        __syncthreads();

        float s[8][8];
        #pragma unroll
        for (int i = 0; i < 8; ++i)
            #pragma unroll
            for (int j = 0; j < 8; ++j) s[i][j] = 0.f;

        #pragma unroll
        for (int dv = 0; dv < 16; ++dv) {
            float4 qv[8];
            #pragma unroll
            for (int i = 0; i < 8; ++i) qv[i] = sQ[swz(trow + i, dv)];
            #pragma unroll
            for (int j = 0; j < 8; ++j) {
                float4 kv = sK[swz(kidx[j], dv)];
                #pragma unroll
                for (int i = 0; i < 8; ++i) {
                    s[i][j] = fmaf(qv[i].x, kv.x, s[i][j]);
                    s[i][j] = fmaf(qv[i].y, kv.y, s[i][j]);
                    s[i][j] = fmaf(qv[i].z, kv.z, s[i][j]);
                    s[i][j] = fmaf(qv[i].w, kv.w, s[i][j]);
                }
            }
        }
        #pragma unroll
        for (int j = 0; j < 8; ++j)
            if (k0 + kidx[j] > SEQ-1) {
                #pragma unroll
                for (int i = 0; i < 8; ++i) s[i][j] = -1e30f;
            }

        // online softmax (row groups = 8 consecutive lanes)
        #pragma unroll
        for (int i = 0; i < 8; ++i) {
            float mloc = s[i][0];
            #pragma unroll
            for (int j = 1; j < 8; ++j) mloc = fmaxf(mloc, s[i][j]);
            mloc = fmaxf(mloc, __shfl_xor_sync(0xffffffffu, mloc, 4));
            mloc = fmaxf(mloc, __shfl_xor_sync(0xffffffffu, mloc, 2));
            mloc = fmaxf(mloc, __shfl_xor_sync(0xffffffffu, mloc, 1));
            float mnew = fmaxf(mrow[i], mloc);
            float corr = __expf(mrow[i] - mnew);
            float rs = 0.f;
            #pragma unroll
            for (int j = 0; j < 8; ++j) {
                float pv = __expf(s[i][j] - mnew);
                s[i][j] = pv; rs += pv;
            }
            rs += __shfl_xor_sync(0xffffffffu, rs, 4);
            rs += __shfl_xor_sync(0xffffffffu, rs, 2);
            rs += __shfl_xor_sync(0xffffffffu, rs, 1);
            lrow[i] = lrow[i]*corr + rs;
            mrow[i] = mnew;
            #pragma unroll
            for (int j = 0; j < 8; ++j) o[i][j] *= corr;
        }

        __syncthreads();                       // S reads of sK done
        float4* sP = sK;                       // P overwrites K tile
        #pragma unroll
        for (int i = 0; i < 8; ++i) {
            sP[swz(trow+i, tc)]   = make_float4(s[i][0], s[i][1], s[i][2], s[i][3]);
            sP[swz(trow+i, tc+8)] = make_float4(s[i][4], s[i][5], s[i][6], s[i][7]);
        }
        __syncthreads();

        #pragma unroll
        for (int mv = 0; mv < 16; ++mv) {
            float4 p4[8];
            #pragma unroll
            for (int i = 0; i < 8; ++i) p4[i] = sP[swz(trow + i, mv)];
            #pragma unroll
            for (int u = 0; u < 4; ++u) {
                float4 va = sV[swz((mv << 2) + u, tc)];
                float4 vb = sV[swz((mv << 2) + u, tc + 8)];
                #pragma unroll
                for (int i = 0; i < 8; ++i) {
                    float pv = (u == 0) ? p4[i].x : (u == 1) ? p4[i].y
                             : (u == 2) ? p4[i].z : p4[i].w;
                    o[i][0] = fmaf(pv, va.x, o[i][0]);
                    o[i][1] = fmaf(pv, va.y, o[i][1]);
                    o[i][2] = fmaf(pv, va.z, o[i][2]);
                    o[i][3] = fmaf(pv, va.w, o[i][3]);
                    o[i][4] = fmaf(pv, vb.x, o[i][4]);
                    o[i][5] = fmaf(pv, vb.y, o[i][5]);
                    o[i][6] = fmaf(pv, vb.z, o[i][6]);
                    o[i][7] = fmaf(pv, vb.w, o[i][7]);
                }
            }
        }
    }

    #pragma unroll
    for (int i = 0; i < 8; ++i) {
        int gr = q0 + trow + i;
        if (gr < SEQ) {
            float inv = 1.0f / lrow[i];
            float* dst = g_o + (b*SEQ + gr)*CH + h*DH;
            *(float4*)(dst + tc*4)      = make_float4(o[i][0]*inv, o[i][1]*inv,
                                                      o[i][2]*inv, o[i][3]*inv);
            *(float4*)(dst + 32 + tc*4) = make_float4(o[i][4]*inv, o[i][5]*inv,
                                                      o[i][6]*inv, o[i][7]*inv);
        }
    }
}

// ---------------------------------------------------------------------------
extern "C" void kernel_launch(void* const* d_in, const int* in_sizes, int n_in,
                              void* d_out, int out_size)
{
    const float* x      = (const float*)d_in[0];
    const float* qkv_w  = (const float*)d_in[1];
    const float* qkv_b  = (const float*)d_in[2];
    const float* proj_w = (const float*)d_in[3];
    const float* proj_b = (const float*)d_in[4];
    float* out = (float*)d_out;

    dim3 g0(QKV_N/128, (MROWS + 127)/128);     // 18 x 145
    sgemm_kernel<0><<<g0, 256>>>(x, qkv_w, qkv_b, nullptr);

    dim3 g1((SEQ + 63)/64, NH, BN);            // 10 x 12 x 32
    attn_kernel<<<g1, 64>>>();

    dim3 g2(CH/128, (MROWS + 127)/128);        // 6 x 145
    sgemm_kernel<1><<<g2, 256>>>(x /*unused*/, proj_w, proj_b, out);
}

// round 3
// speedup vs baseline: 1.2767x; 1.2767x over previous
#include <cuda_runtime.h>
#include <cuda_bf16.h>
#include <cstdint>

#define BN   32
#define SEQ  577
#define CH   768
#define NH   12
#define DH   64
#define MROWS (BN*SEQ)      /* 18464 */
#define QKV_N (3*CH)        /* 2304  */

// ---------------- scratch (__device__ globals; no allocs allowed) ----------
__device__ float g_q[BN*NH*SEQ*DH];
__device__ float g_k[BN*NH*SEQ*DH];
__device__ float g_v[BN*NH*SEQ*DH];
__device__ float g_o[BN*SEQ*CH];
__device__ __nv_bfloat16 g_xh[MROWS*CH], g_xl[MROWS*CH];   // A hi/lo (x, then attn out)
__device__ __nv_bfloat16 g_wh[QKV_N*CH], g_wl[QKV_N*CH];   // qkv_w hi/lo
__device__ __nv_bfloat16 g_ph[CH*CH],   g_pl[CH*CH];       // proj_w hi/lo

// ---------------- helpers ---------------------------------------------------
__device__ __forceinline__ uint32_t smem_u32(const void* p) {
    uint32_t a;
    asm("{ .reg .u64 t; cvta.to.shared.u64 t, %1; cvt.u32.u64 %0, t; }" : "=r"(a) : "l"(p));
    return a;
}
__device__ __forceinline__ void ldsm_x4(uint32_t& r0, uint32_t& r1,
                                        uint32_t& r2, uint32_t& r3, uint32_t addr) {
    asm volatile("ldmatrix.sync.aligned.m8n8.x4.shared.b16 {%0,%1,%2,%3}, [%4];"
                 : "=r"(r0), "=r"(r1), "=r"(r2), "=r"(r3) : "r"(addr));
}
__device__ __forceinline__ void mma16816(float* c, const uint32_t* a, const uint32_t* b) {
    asm volatile("mma.sync.aligned.m16n8k16.row.col.f32.bf16.bf16.f32 "
                 "{%0,%1,%2,%3}, {%4,%5,%6,%7}, {%8,%9}, {%0,%1,%2,%3};"
                 : "+f"(c[0]), "+f"(c[1]), "+f"(c[2]), "+f"(c[3])
                 : "r"(a[0]), "r"(a[1]), "r"(a[2]), "r"(a[3]), "r"(b[0]), "r"(b[1]));
}
// tile row r (0..127), 16B-chunk c (0..3); 64B rows, XOR swizzle (conflict-free ldmatrix)
__device__ __forceinline__ uint32_t swoff(int r, int c) {
    return (uint32_t)(r * 64 + ((c ^ ((r >> 1) & 3)) << 4));
}

// ---------------- split: fp32 -> bf16 hi + bf16 lo -------------------------
__global__ void split_kernel(const float* __restrict__ src, int sel, int n) {
    int i = blockIdx.x * 256 + threadIdx.x;
    if (i >= n) return;
    float v = (sel == 3) ? g_o[i] : src[i];
    __nv_bfloat16 h = __float2bfloat16(v);
    __nv_bfloat16 l = __float2bfloat16(v - __bfloat162float(h));
    if (sel == 0 || sel == 3) { g_xh[i] = h; g_xl[i] = l; }
    else if (sel == 1)        { g_wh[i] = h; g_wl[i] = l; }
    else                      { g_ph[i] = h; g_pl[i] = l; }
}

// ---------------- mma.sync bf16x3 GEMM --------------------------------------
// D[128x128] = A[128x768] * B[128x768]^T (B row-major [N,K]).
// MODE 0: A=x(split), B=qkv_w(split) -> scatter g_q/g_k/g_v (+bias, q*0.125)
// MODE 1: A=attn-out(split), B=proj_w(split) -> out (+bias)
template<int MODE>
__global__ __launch_bounds__(256) void mma_gemm(const float* __restrict__ bias,
                                                float* __restrict__ out)
{
    __shared__ __align__(16) char smem[32768];
    const uint32_t sb = smem_u32(smem);
    const int tid = threadIdx.x, lane = tid & 31, wid = tid >> 5;
    const int wm = wid & 1, wn = wid >> 1;          // 2 x 4 warp grid
    const int tileN = blockIdx.x, tileM = blockIdx.y;

    const __nv_bfloat16* __restrict__ Ah = g_xh;
    const __nv_bfloat16* __restrict__ Al = g_xl;
    const __nv_bfloat16* __restrict__ Bh = (MODE == 0) ? g_wh : g_ph;
    const __nv_bfloat16* __restrict__ Bl = (MODE == 0) ? g_wl : g_pl;

    const uint32_t OFF_AH = 0, OFF_AL = 8192, OFF_BH = 16384, OFF_BL = 24576;

    // loader: thread -> (row lr, chunk pair lc) ; 16B chunks, 32B/thread/buffer
    const int lr = tid >> 1;
    const int lc = (tid & 1) << 1;
    int ga = tileM * 128 + lr; if (ga > MROWS - 1) ga = MROWS - 1;
    const int gb = tileN * 128 + lr;
    const size_t abase = (size_t)ga * CH + lc * 8;
    const size_t bbase = (size_t)gb * CH + lc * 8;

    float acc[4][4][4];
    #pragma unroll
    for (int i = 0; i < 4; ++i)
        #pragma unroll
        for (int j = 0; j < 4; ++j)
            #pragma unroll
            for (int r = 0; r < 4; ++r) acc[i][j][r] = 0.f;

    int4 pah[2], pal[2], pbh[2], pbl[2];
    {
        pah[0] = *(const int4*)(Ah + abase); pah[1] = *(const int4*)(Ah + abase + 8);
        pal[0] = *(const int4*)(Al + abase); pal[1] = *(const int4*)(Al + abase + 8);
        pbh[0] = *(const int4*)(Bh + bbase); pbh[1] = *(const int4*)(Bh + bbase + 8);
        pbl[0] = *(const int4*)(Bl + bbase); pbl[1] = *(const int4*)(Bl + bbase + 8);
    }

    const uint32_t so0 = swoff(lr, lc), so1 = swoff(lr, lc + 1);

    for (int kc = 0; kc < 24; ++kc) {
        __syncthreads();                 // prior iter done reading smem
        *(int4*)(smem + OFF_AH + so0) = pah[0]; *(int4*)(smem + OFF_AH + so1) = pah[1];
        *(int4*)(smem + OFF_AL + so0) = pal[0]; *(int4*)(smem + OFF_AL + so1) = pal[1];
        *(int4*)(smem + OFF_BH + so0) = pbh[0]; *(int4*)(smem + OFF_BH + so1) = pbh[1];
        *(int4*)(smem + OFF_BL + so0) = pbl[0]; *(int4*)(smem + OFF_BL + so1) = pbl[1];
        __syncthreads();

        if (kc + 1 < 24) {               // prefetch next chunk (overlaps HMMAs)
            size_t ao = abase + (size_t)(kc + 1) * 32;
            size_t bo = bbase + (size_t)(kc + 1) * 32;
            pah[0] = *(const int4*)(Ah + ao); pah[1] = *(const int4*)(Ah + ao + 8);
            pal[0] = *(const int4*)(Al + ao); pal[1] = *(const int4*)(Al + ao + 8);
            pbh[0] = *(const int4*)(Bh + bo); pbh[1] = *(const int4*)(Bh + bo + 8);
            pbl[0] = *(const int4*)(Bl + bo); pbl[1] = *(const int4*)(Bl + bo + 8);
        }

        #pragma unroll
        for (int k16 = 0; k16 < 2; ++k16) {
            uint32_t ah[4][4], al[4][4];
            #pragma unroll
            for (int mf = 0; mf < 4; ++mf) {
                int row = wm * 64 + mf * 16 + (lane & 15);
                int c   = 2 * k16 + (lane >> 4);
                uint32_t o = swoff(row, c);
                ldsm_x4(ah[mf][0], ah[mf][1], ah[mf][2], ah[mf][3], sb + OFF_AH + o);
                ldsm_x4(al[mf][0], al[mf][1], al[mf][2], al[mf][3], sb + OFF_AL + o);
            }
            uint32_t bh[4][2], bl[4][2];
            #pragma unroll
            for (int np = 0; np < 2; ++np) {
                int g = lane >> 3, l = lane & 7;
                int row = wn * 32 + np * 16 + (g >> 1) * 8 + l;
                int c   = 2 * k16 + (g & 1);
                uint32_t o = swoff(row, c);
                ldsm_x4(bh[np*2][0], bh[np*2][1], bh[np*2+1][0], bh[np*2+1][1],
                        sb + OFF_BH + o);
                ldsm_x4(bl[np*2][0], bl[np*2][1], bl[np*2+1][0], bl[np*2+1][1],
                        sb + OFF_BL + o);
            }
            #pragma unroll
            for (int mf = 0; mf < 4; ++mf)
                #pragma unroll
                for (int nf = 0; nf < 4; ++nf) {
                    mma16816(acc[mf][nf], ah[mf], bh[nf]);
                    mma16816(acc[mf][nf], ah[mf], bl[nf]);
                    mma16816(acc[mf][nf], al[mf], bh[nf]);
                }
        }
    }

    // ---------------- epilogue ----------------
    const int s = (MODE == 0) ? (tileN * 128) / CH : 0;
    float* basep = (MODE == 0) ? ((s == 0) ? g_q : (s == 1) ? g_k : g_v) : out;
    const float scl = (MODE == 0 && s == 0) ? 0.125f : 1.0f;

    #pragma unroll
    for (int mf = 0; mf < 4; ++mf) {
        const int rbase = tileM * 128 + wm * 64 + mf * 16 + (lane >> 2);
        #pragma unroll
        for (int nf = 0; nf < 4; ++nf) {
            const int gcol = tileN * 128 + wn * 32 + nf * 8 + ((lane & 3) << 1);
            const float b0 = bias[gcol], b1 = bias[gcol + 1];
            #pragma unroll
            for (int hh = 0; hh < 2; ++hh) {
                const int row = rbase + hh * 8;
                if (row >= MROWS) continue;
                float v0 = (acc[mf][nf][hh*2+0] + b0) * scl;
                float v1 = (acc[mf][nf][hh*2+1] + b1) * scl;
                if (MODE == 0) {
                    int rem = gcol - s * CH;
                    int h = rem >> 6, d = rem & 63;
                    int b = row / SEQ, n = row - b * SEQ;
                    float* dst = basep + ((size_t)(b * NH + h) * SEQ + n) * DH + d;
                    *(float2*)dst = make_float2(v0, v1);
                } else {
                    float* dst = out + (size_t)row * CH + gcol;
                    *(float2*)dst = make_float2(v0, v1);
                }
            }
        }
    }
}

// ---------------- flash attention (unchanged v1) ---------------------------
__device__ __forceinline__ int swz(int r, int c4) {
    return (r << 4) + (c4 ^ ((r >> 2) & 7));
}

__global__ __launch_bounds__(64) void attn_kernel()
{
    __shared__ float4 sQ[1024];
    __shared__ float4 sK[1024];
    __shared__ float4 sV[1024];

    const int tid = threadIdx.x;
    const int q0  = blockIdx.x << 6;
    const int h   = blockIdx.y, b = blockIdx.z;
    const int bh  = b*NH + h;
    const float* Qb = g_q + bh*SEQ*DH;
    const float* Kb = g_k + bh*SEQ*DH;
    const float* Vb = g_v + bh*SEQ*DH;
    const int trow = (tid >> 3) << 3;
    const int tc   = tid & 7;

    #pragma unroll
    for (int p = 0; p < 16; ++p) {
        int f = tid + (p << 6);
        int r = f >> 4, c4 = f & 15;
        int gr = q0 + r; if (gr > SEQ-1) gr = SEQ-1;
        sQ[swz(r, c4)] = *(const float4*)(Qb + gr*DH + (c4 << 2));
    }

    float o[8][8];
    float mrow[8], lrow[8];
    #pragma unroll
    for (int i = 0; i < 8; ++i) {
        mrow[i] = -1e30f; lrow[i] = 0.f;
        #pragma unroll
        for (int j = 0; j < 8; ++j) o[i][j] = 0.f;
    }

    int kidx[8];
    #pragma unroll
    for (int j = 0; j < 8; ++j) kidx[j] = (j < 4) ? (tc*4 + j) : (28 + tc*4 + j);

    for (int kt = 0; kt < 10; ++kt) {
        const int k0 = kt << 6;
        __syncthreads();
        #pragma unroll
        for (int p = 0; p < 16; ++p) {
            int f = tid + (p << 6);
            int r = f >> 4, c4 = f & 15;
            int gr = k0 + r; if (gr > SEQ-1) gr = SEQ-1;
            sK[swz(r, c4)] = *(const float4*)(Kb + gr*DH + (c4 << 2));
            sV[swz(r, c4)] = *(const float4*)(Vb + gr*DH + (c4 << 2));
        }
        __syncthreads();

        float s[8][8];
        #pragma unroll
        for (int i = 0; i < 8; ++i)
            #pragma unroll
            for (int j = 0; j < 8; ++j) s[i][j] = 0.f;

        #pragma unroll
        for (int dv = 0; dv < 16; ++dv) {
            float4 qv[8];
            #pragma unroll
            for (int i = 0; i < 8; ++i) qv[i] = sQ[swz(trow + i, dv)];
            #pragma unroll
            for (int j = 0; j < 8; ++j) {
                float4 kv = sK[swz(kidx[j], dv)];
                #pragma unroll
                for (int i = 0; i < 8; ++i) {
                    s[i][j] = fmaf(qv[i].x, kv.x, s[i][j]);
                    s[i][j] = fmaf(qv[i].y, kv.y, s[i][j]);
                    s[i][j] = fmaf(qv[i].z, kv.z, s[i][j]);
                    s[i][j] = fmaf(qv[i].w, kv.w, s[i][j]);
                }
            }
        }
        #pragma unroll
        for (int j = 0; j < 8; ++j)
            if (k0 + kidx[j] > SEQ-1) {
                #pragma unroll
                for (int i = 0; i < 8; ++i) s[i][j] = -1e30f;
            }

        #pragma unroll
        for (int i = 0; i < 8; ++i) {
            float mloc = s[i][0];
            #pragma unroll
            for (int j = 1; j < 8; ++j) mloc = fmaxf(mloc, s[i][j]);
            mloc = fmaxf(mloc, __shfl_xor_sync(0xffffffffu, mloc, 4));
            mloc = fmaxf(mloc, __shfl_xor_sync(0xffffffffu, mloc, 2));
            mloc = fmaxf(mloc, __shfl_xor_sync(0xffffffffu, mloc, 1));
            float mnew = fmaxf(mrow[i], mloc);
            float corr = __expf(mrow[i] - mnew);
            float rs = 0.f;
            #pragma unroll
            for (int j = 0; j < 8; ++j) {
                float pv = __expf(s[i][j] - mnew);
                s[i][j] = pv; rs += pv;
            }
            rs += __shfl_xor_sync(0xffffffffu, rs, 4);
            rs += __shfl_xor_sync(0xffffffffu, rs, 2);
            rs += __shfl_xor_sync(0xffffffffu, rs, 1);
            lrow[i] = lrow[i]*corr + rs;
            mrow[i] = mnew;
            #pragma unroll
            for (int j = 0; j < 8; ++j) o[i][j] *= corr;
        }

        __syncthreads();
        float4* sP = sK;
        #pragma unroll
        for (int i = 0; i < 8; ++i) {
            sP[swz(trow+i, tc)]   = make_float4(s[i][0], s[i][1], s[i][2], s[i][3]);
            sP[swz(trow+i, tc+8)] = make_float4(s[i][4], s[i][5], s[i][6], s[i][7]);
        }
        __syncthreads();

        #pragma unroll
        for (int mv = 0; mv < 16; ++mv) {
            float4 p4[8];
            #pragma unroll
            for (int i = 0; i < 8; ++i) p4[i] = sP[swz(trow + i, mv)];
            #pragma unroll
            for (int u = 0; u < 4; ++u) {
                float4 va = sV[swz((mv << 2) + u, tc)];
                float4 vb = sV[swz((mv << 2) + u, tc + 8)];
                #pragma unroll
                for (int i = 0; i < 8; ++i) {
                    float pv = (u == 0) ? p4[i].x : (u == 1) ? p4[i].y
                             : (u == 2) ? p4[i].z : p4[i].w;
                    o[i][0] = fmaf(pv, va.x, o[i][0]);
                    o[i][1] = fmaf(pv, va.y, o[i][1]);
                    o[i][2] = fmaf(pv, va.z, o[i][2]);
                    o[i][3] = fmaf(pv, va.w, o[i][3]);
                    o[i][4] = fmaf(pv, vb.x, o[i][4]);
                    o[i][5] = fmaf(pv, vb.y, o[i][5]);
                    o[i][6] = fmaf(pv, vb.z, o[i][6]);
                    o[i][7] = fmaf(pv, vb.w, o[i][7]);
                }
            }
        }
    }

    #pragma unroll
    for (int i = 0; i < 8; ++i) {
        int gr = q0 + trow + i;
        if (gr < SEQ) {
            float inv = 1.0f / lrow[i];
            float* dst = g_o + (b*SEQ + gr)*CH + h*DH;
            *(float4*)(dst + tc*4)      = make_float4(o[i][0]*inv, o[i][1]*inv,
                                                      o[i][2]*inv, o[i][3]*inv);
            *(float4*)(dst + 32 + tc*4) = make_float4(o[i][4]*inv, o[i][5]*inv,
                                                      o[i][6]*inv, o[i][7]*inv);
        }
    }
}

// ---------------------------------------------------------------------------
extern "C" void kernel_launch(void* const* d_in, const int* in_sizes, int n_in,
                              void* d_out, int out_size)
{
    const float* x      = (const float*)d_in[0];
    const float* qkv_w  = (const float*)d_in[1];
    const float* qkv_b  = (const float*)d_in[2];
    const float* proj_w = (const float*)d_in[3];
    const float* proj_b = (const float*)d_in[4];
    float* out = (float*)d_out;

    // split x and both weight matrices to bf16 hi/lo
    split_kernel<<<(MROWS*CH + 255)/256, 256>>>(x, 0, MROWS*CH);
    split_kernel<<<(QKV_N*CH + 255)/256, 256>>>(qkv_w, 1, QKV_N*CH);
    split_kernel<<<(CH*CH + 255)/256, 256>>>(proj_w, 2, CH*CH);

    // QKV GEMM (tensor cores via mma.sync) -> g_q/g_k/g_v
    mma_gemm<0><<<dim3(QKV_N/128, (MROWS + 127)/128), 256>>>(qkv_b, nullptr);

    // attention -> g_o
    dim3 g1((SEQ + 63)/64, NH, BN);
    attn_kernel<<<g1, 64>>>();

    // split attention output, then proj GEMM -> out
    split_kernel<<<(MROWS*CH + 255)/256, 256>>>(nullptr, 3, MROWS*CH);
    mma_gemm<1><<<dim3(CH/128, (MROWS + 127)/128), 256>>>(proj_b, out);
}

// round 4
// speedup vs baseline: 3.3295x; 2.6078x over previous
#include <cuda_runtime.h>
#include <cuda_bf16.h>
#include <cstdint>

#define BN   32
#define SEQ  577
#define CH   768
#define NH   12
#define DH   64
#define MROWS (BN*SEQ)      /* 18464 */
#define QKV_N (3*CH)        /* 2304  */
#define QT   128
#define KT   128
#define NKT  5              /* ceil(577/128) */

// ---------------- scratch (__device__ globals; no allocs allowed) ----------
__device__ __nv_bfloat16 g_qh[BN*NH*SEQ*DH], g_ql[BN*NH*SEQ*DH];
__device__ __nv_bfloat16 g_kh[BN*NH*SEQ*DH], g_kl[BN*NH*SEQ*DH];
__device__ __nv_bfloat16 g_vh[BN*NH*SEQ*DH], g_vl[BN*NH*SEQ*DH];
__device__ __nv_bfloat16 g_xh[MROWS*CH], g_xl[MROWS*CH];   // A hi/lo (x, then attn out)
__device__ __nv_bfloat16 g_wh[QKV_N*CH], g_wl[QKV_N*CH];   // qkv_w hi/lo
__device__ __nv_bfloat16 g_ph[CH*CH],   g_pl[CH*CH];       // proj_w hi/lo

// ---------------- helpers ---------------------------------------------------
__device__ __forceinline__ uint32_t smem_u32(const void* p) {
    uint32_t a;
    asm("{ .reg .u64 t; cvta.to.shared.u64 t, %1; cvt.u32.u64 %0, t; }" : "=r"(a) : "l"(p));
    return a;
}
__device__ __forceinline__ void ldsm_x4(uint32_t& r0, uint32_t& r1,
                                        uint32_t& r2, uint32_t& r3, uint32_t addr) {
    asm volatile("ldmatrix.sync.aligned.m8n8.x4.shared.b16 {%0,%1,%2,%3}, [%4];"
                 : "=r"(r0), "=r"(r1), "=r"(r2), "=r"(r3) : "r"(addr));
}
__device__ __forceinline__ void ldsm_x4_t(uint32_t& r0, uint32_t& r1,
                                          uint32_t& r2, uint32_t& r3, uint32_t addr) {
    asm volatile("ldmatrix.sync.aligned.m8n8.x4.trans.shared.b16 {%0,%1,%2,%3}, [%4];"
                 : "=r"(r0), "=r"(r1), "=r"(r2), "=r"(r3) : "r"(addr));
}
__device__ __forceinline__ void mma16816(float* c, const uint32_t* a, const uint32_t* b) {
    asm volatile("mma.sync.aligned.m16n8k16.row.col.f32.bf16.bf16.f32 "
                 "{%0,%1,%2,%3}, {%4,%5,%6,%7}, {%8,%9}, {%0,%1,%2,%3};"
                 : "+f"(c[0]), "+f"(c[1]), "+f"(c[2]), "+f"(c[3])
                 : "r"(a[0]), "r"(a[1]), "r"(a[2]), "r"(a[3]), "r"(b[0]), "r"(b[1]));
}
__device__ __forceinline__ void mma2(float* c, const uint32_t* a, uint32_t b0, uint32_t b1) {
    asm volatile("mma.sync.aligned.m16n8k16.row.col.f32.bf16.bf16.f32 "
                 "{%0,%1,%2,%3}, {%4,%5,%6,%7}, {%8,%9}, {%0,%1,%2,%3};"
                 : "+f"(c[0]), "+f"(c[1]), "+f"(c[2]), "+f"(c[3])
                 : "r"(a[0]), "r"(a[1]), "r"(a[2]), "r"(a[3]), "r"(b0), "r"(b1));
}
// GEMM tile swizzle: 64B rows, 4 chunks
__device__ __forceinline__ uint32_t swoff(int r, int c) {
    return (uint32_t)(r * 64 + ((c ^ ((r >> 1) & 3)) << 4));
}
// attention tile swizzle: 128B rows, 8 chunks
__device__ __forceinline__ uint32_t aswz(int r, int c) {
    return (uint32_t)(r * 128 + ((c ^ (r & 7)) << 4));
}
// fp32 pair -> bf16 hi pair + bf16 lo pair (packed u32)
__device__ __forceinline__ void split2(float x, float y, uint32_t& hi, uint32_t& lo) {
    __nv_bfloat162 h2 = __floats2bfloat162_rn(x, y);
    __nv_bfloat162 l2 = __floats2bfloat162_rn(x - __bfloat162float(h2.x),
                                              y - __bfloat162float(h2.y));
    hi = reinterpret_cast<uint32_t&>(h2);
    lo = reinterpret_cast<uint32_t&>(l2);
}

// ---------------- split: fp32 -> bf16 hi + bf16 lo -------------------------
__global__ void split_kernel(const float* __restrict__ src, int sel, int n) {
    int i = blockIdx.x * 256 + threadIdx.x;
    if (i >= n) return;
    float v = src[i];
    __nv_bfloat16 h = __float2bfloat16(v);
    __nv_bfloat16 l = __float2bfloat16(v - __bfloat162float(h));
    if (sel == 0)      { g_xh[i] = h; g_xl[i] = l; }
    else if (sel == 1) { g_wh[i] = h; g_wl[i] = l; }
    else               { g_ph[i] = h; g_pl[i] = l; }
}

// ---------------- mma.sync bf16x3 GEMM --------------------------------------
// MODE 0: A=x(split), B=qkv_w(split) -> g_{q,k,v}{h,l} bf16 (+bias, q*0.125)
// MODE 1: A=attn-out(split in g_x{h,l}), B=proj_w(split) -> out (+bias)
template<int MODE>
__global__ __launch_bounds__(256) void mma_gemm(const float* __restrict__ bias,
                                                float* __restrict__ out)
{
    __shared__ __align__(16) char smem[32768];
    const uint32_t sb = smem_u32(smem);
    const int tid = threadIdx.x, lane = tid & 31, wid = tid >> 5;
    const int wm = wid & 1, wn = wid >> 1;
    const int tileN = blockIdx.x, tileM = blockIdx.y;

    const __nv_bfloat16* __restrict__ Ah = g_xh;
    const __nv_bfloat16* __restrict__ Al = g_xl;
    const __nv_bfloat16* __restrict__ Bh = (MODE == 0) ? g_wh : g_ph;
    const __nv_bfloat16* __restrict__ Bl = (MODE == 0) ? g_wl : g_pl;

    const uint32_t OFF_AH = 0, OFF_AL = 8192, OFF_BH = 16384, OFF_BL = 24576;

    const int lr = tid >> 1;
    const int lc = (tid & 1) << 1;
    int ga = tileM * 128 + lr; if (ga > MROWS - 1) ga = MROWS - 1;
    const int gb = tileN * 128 + lr;
    const size_t abase = (size_t)ga * CH + lc * 8;
    const size_t bbase = (size_t)gb * CH + lc * 8;

    float acc[4][4][4];
    #pragma unroll
    for (int i = 0; i < 4; ++i)
        #pragma unroll
        for (int j = 0; j < 4; ++j)
            #pragma unroll
            for (int r = 0; r < 4; ++r) acc[i][j][r] = 0.f;

    int4 pah[2], pal[2], pbh[2], pbl[2];
    pah[0] = *(const int4*)(Ah + abase); pah[1] = *(const int4*)(Ah + abase + 8);
    pal[0] = *(const int4*)(Al + abase); pal[1] = *(const int4*)(Al + abase + 8);
    pbh[0] = *(const int4*)(Bh + bbase); pbh[1] = *(const int4*)(Bh + bbase + 8);
    pbl[0] = *(const int4*)(Bl + bbase); pbl[1] = *(const int4*)(Bl + bbase + 8);

    const uint32_t so0 = swoff(lr, lc), so1 = swoff(lr, lc + 1);

    for (int kc = 0; kc < 24; ++kc) {
        __syncthreads();
        *(int4*)(smem + OFF_AH + so0) = pah[0]; *(int4*)(smem + OFF_AH + so1) = pah[1];
        *(int4*)(smem + OFF_AL + so0) = pal[0]; *(int4*)(smem + OFF_AL + so1) = pal[1];
        *(int4*)(smem + OFF_BH + so0) = pbh[0]; *(int4*)(smem + OFF_BH + so1) = pbh[1];
        *(int4*)(smem + OFF_BL + so0) = pbl[0]; *(int4*)(smem + OFF_BL + so1) = pbl[1];
        __syncthreads();

        if (kc + 1 < 24) {
            size_t ao = abase + (size_t)(kc + 1) * 32;
            size_t bo = bbase + (size_t)(kc + 1) * 32;
            pah[0] = *(const int4*)(Ah + ao); pah[1] = *(const int4*)(Ah + ao + 8);
            pal[0] = *(const int4*)(Al + ao); pal[1] = *(const int4*)(Al + ao + 8);
            pbh[0] = *(const int4*)(Bh + bo); pbh[1] = *(const int4*)(Bh + bo + 8);
            pbl[0] = *(const int4*)(Bl + bo); pbl[1] = *(const int4*)(Bl + bo + 8);
        }

        #pragma unroll
        for (int k16 = 0; k16 < 2; ++k16) {
            uint32_t ah[4][4], al[4][4];
            #pragma unroll
            for (int mf = 0; mf < 4; ++mf) {
                int row = wm * 64 + mf * 16 + (lane & 15);
                int c   = 2 * k16 + (lane >> 4);
                uint32_t o = swoff(row, c);
                ldsm_x4(ah[mf][0], ah[mf][1], ah[mf][2], ah[mf][3], sb + OFF_AH + o);
                ldsm_x4(al[mf][0], al[mf][1], al[mf][2], al[mf][3], sb + OFF_AL + o);
            }
            uint32_t bh[4][2], bl[4][2];
            #pragma unroll
            for (int np = 0; np < 2; ++np) {
                int g = lane >> 3, l = lane & 7;
                int row = wn * 32 + np * 16 + (g >> 1) * 8 + l;
                int c   = 2 * k16 + (g & 1);
                uint32_t o = swoff(row, c);
                ldsm_x4(bh[np*2][0], bh[np*2][1], bh[np*2+1][0], bh[np*2+1][1],
                        sb + OFF_BH + o);
                ldsm_x4(bl[np*2][0], bl[np*2][1], bl[np*2+1][0], bl[np*2+1][1],
                        sb + OFF_BL + o);
            }
            #pragma unroll
            for (int mf = 0; mf < 4; ++mf)
                #pragma unroll
                for (int nf = 0; nf < 4; ++nf) {
                    mma16816(acc[mf][nf], ah[mf], bh[nf]);
                    mma16816(acc[mf][nf], ah[mf], bl[nf]);
                    mma16816(acc[mf][nf], al[mf], bh[nf]);
                }
        }
    }

    // ---------------- epilogue ----------------
    const int s = (MODE == 0) ? (tileN * 128) / CH : 0;
    const float scl = (MODE == 0 && s == 0) ? 0.125f : 1.0f;

    #pragma unroll
    for (int mf = 0; mf < 4; ++mf) {
        const int rbase = tileM * 128 + wm * 64 + mf * 16 + (lane >> 2);
        #pragma unroll
        for (int nf = 0; nf < 4; ++nf) {
            const int gcol = tileN * 128 + wn * 32 + nf * 8 + ((lane & 3) << 1);
            const float b0 = bias[gcol], b1 = bias[gcol + 1];
            #pragma unroll
            for (int hh = 0; hh < 2; ++hh) {
                const int row = rbase + hh * 8;
                if (row >= MROWS) continue;
                float v0 = (acc[mf][nf][hh*2+0] + b0) * scl;
                float v1 = (acc[mf][nf][hh*2+1] + b1) * scl;
                if (MODE == 0) {
                    int rem = gcol - s * CH;
                    int hd = rem >> 6, d = rem & 63;
                    int bb = row / SEQ, n = row - bb * SEQ;
                    size_t di = ((size_t)(bb * NH + hd) * SEQ + n) * DH + d;
                    __nv_bfloat16 *dsth, *dstl;
                    if (s == 0)      { dsth = g_qh; dstl = g_ql; }
                    else if (s == 1) { dsth = g_kh; dstl = g_kl; }
                    else             { dsth = g_vh; dstl = g_vl; }
                    uint32_t hp, lp;
                    split2(v0, v1, hp, lp);
                    *(uint32_t*)(dsth + di) = hp;
                    *(uint32_t*)(dstl + di) = lp;
                } else {
                    *(float2*)(out + (size_t)row * CH + gcol) = make_float2(v0, v1);
                }
            }
        }
    }
}

// ---------------- mma.sync flash attention ----------------------------------
// block = (qtile, h, b), 256 thr / 8 warps; warp w owns q rows w*16..w*16+15.
// S = Q*K^T (x3 split), online softmax in regs, P repacked in-reg, PV (x3).
#define ATT_QH 0
#define ATT_QL 16384
#define ATT_KH 32768
#define ATT_KL 49152
#define ATT_VH 65536
#define ATT_VL 81920
#define ATT_SMEM 98304

__global__ __launch_bounds__(256) void attn_mma()
{
    extern __shared__ char sm[];
    const uint32_t sb = smem_u32(sm);
    const int tid = threadIdx.x, lane = tid & 31, w = tid >> 5;
    const int q0 = blockIdx.x * QT;
    const int hh = blockIdx.y, b = blockIdx.z;
    const size_t hb = (size_t)(b * NH + hh) * SEQ;

    // load Q tile (hi/lo), swizzled
    #pragma unroll
    for (int p = 0; p < 4; ++p) {
        int slot = tid + p * 256;
        int r = slot >> 3, c = slot & 7;
        int gr = q0 + r; if (gr > SEQ - 1) gr = SEQ - 1;
        size_t idx = ((hb + gr) << 6) + c * 8;
        uint32_t so = aswz(r, c);
        *(int4*)(sm + ATT_QH + so) = *(const int4*)(g_qh + idx);
        *(int4*)(sm + ATT_QL + so) = *(const int4*)(g_ql + idx);
    }
    __syncthreads();

    // Q fragments in registers (4 k16 steps over DH)
    uint32_t qh[4][4], ql[4][4];
    #pragma unroll
    for (int kd = 0; kd < 4; ++kd) {
        int row = w * 16 + (lane & 15);
        int c = 2 * kd + (lane >> 4);
        uint32_t o = aswz(row, c);
        ldsm_x4(qh[kd][0], qh[kd][1], qh[kd][2], qh[kd][3], sb + ATT_QH + o);
        ldsm_x4(ql[kd][0], ql[kd][1], ql[kd][2], ql[kd][3], sb + ATT_QL + o);
    }

    float o[8][4];
    #pragma unroll
    for (int i = 0; i < 8; ++i)
        #pragma unroll
        for (int j = 0; j < 4; ++j) o[i][j] = 0.f;
    float m0 = -1e30f, m1 = -1e30f, l0 = 0.f, l1 = 0.f;

    for (int kt = 0; kt < NKT; ++kt) {
        const int k0 = kt * KT;
        __syncthreads();
        #pragma unroll
        for (int p = 0; p < 4; ++p) {
            int slot = tid + p * 256;
            int r = slot >> 3, c = slot & 7;
            int gk = k0 + r; if (gk > SEQ - 1) gk = SEQ - 1;
            size_t idx = ((hb + gk) << 6) + c * 8;
            uint32_t so = aswz(r, c);
            *(int4*)(sm + ATT_KH + so) = *(const int4*)(g_kh + idx);
            *(int4*)(sm + ATT_KL + so) = *(const int4*)(g_kl + idx);
            *(int4*)(sm + ATT_VH + so) = *(const int4*)(g_vh + idx);
            *(int4*)(sm + ATT_VL + so) = *(const int4*)(g_vl + idx);
        }
        __syncthreads();

        // ---- S = Q K^T ----
        float s[16][4];
        #pragma unroll
        for (int i = 0; i < 16; ++i)
            #pragma unroll
            for (int j = 0; j < 4; ++j) s[i][j] = 0.f;

        #pragma unroll
        for (int kp = 0; kp < 8; ++kp) {
            #pragma unroll
            for (int kd = 0; kd < 4; ++kd) {
                int g = lane >> 3, li = lane & 7;
                int row = kp * 16 + ((g >> 1) << 3) + li;
                int c = 2 * kd + (g & 1);
                uint32_t so = aswz(row, c);
                uint32_t kh4[4], kl4[4];
                ldsm_x4(kh4[0], kh4[1], kh4[2], kh4[3], sb + ATT_KH + so);
                ldsm_x4(kl4[0], kl4[1], kl4[2], kl4[3], sb + ATT_KL + so);
                mma2(s[2*kp],   qh[kd], kh4[0], kh4[1]);
                mma2(s[2*kp],   qh[kd], kl4[0], kl4[1]);
                mma2(s[2*kp],   ql[kd], kh4[0], kh4[1]);
                mma2(s[2*kp+1], qh[kd], kh4[2], kh4[3]);
                mma2(s[2*kp+1], qh[kd], kl4[2], kl4[3]);
                mma2(s[2*kp+1], ql[kd], kh4[2], kh4[3]);
            }
        }

        // mask invalid keys (last tile)
        if (k0 + KT > SEQ) {
            #pragma unroll
            for (int kn = 0; kn < 16; ++kn) {
                int kg = k0 + kn * 8 + ((lane & 3) << 1);
                if (kg >= SEQ)     { s[kn][0] = -1e30f; s[kn][2] = -1e30f; }
                if (kg + 1 >= SEQ) { s[kn][1] = -1e30f; s[kn][3] = -1e30f; }
            }
        }

        // ---- online softmax ----
        float mx0 = -1e30f, mx1 = -1e30f;
        #pragma unroll
        for (int kn = 0; kn < 16; ++kn) {
            mx0 = fmaxf(mx0, fmaxf(s[kn][0], s[kn][1]));
            mx1 = fmaxf(mx1, fmaxf(s[kn][2], s[kn][3]));
        }
        mx0 = fmaxf(mx0, __shfl_xor_sync(0xffffffffu, mx0, 1));
        mx0 = fmaxf(mx0, __shfl_xor_sync(0xffffffffu, mx0, 2));
        mx1 = fmaxf(mx1, __shfl_xor_sync(0xffffffffu, mx1, 1));
        mx1 = fmaxf(mx1, __shfl_xor_sync(0xffffffffu, mx1, 2));
        float mn0 = fmaxf(m0, mx0), mn1 = fmaxf(m1, mx1);
        float c0 = __expf(m0 - mn0), c1 = __expf(m1 - mn1);
        float sum0 = 0.f, sum1 = 0.f;
        #pragma unroll
        for (int kn = 0; kn < 16; ++kn) {
            s[kn][0] = __expf(s[kn][0] - mn0);
            s[kn][1] = __expf(s[kn][1] - mn0);
            s[kn][2] = __expf(s[kn][2] - mn1);
            s[kn][3] = __expf(s[kn][3] - mn1);
            sum0 += s[kn][0] + s[kn][1];
            sum1 += s[kn][2] + s[kn][3];
        }
        sum0 += __shfl_xor_sync(0xffffffffu, sum0, 1);
        sum0 += __shfl_xor_sync(0xffffffffu, sum0, 2);
        sum1 += __shfl_xor_sync(0xffffffffu, sum1, 1);
        sum1 += __shfl_xor_sync(0xffffffffu, sum1, 2);
        l0 = l0 * c0 + sum0; l1 = l1 * c1 + sum1;
        m0 = mn0; m1 = mn1;
        #pragma unroll
        for (int nf = 0; nf < 8; ++nf) {
            o[nf][0] *= c0; o[nf][1] *= c0;
            o[nf][2] *= c1; o[nf][3] *= c1;
        }

        // ---- PV: O += P V  (P packed from S regs) ----
        #pragma unroll
        for (int kk = 0; kk < 8; ++kk) {
            uint32_t ah[4], al[4];
            split2(s[2*kk][0],   s[2*kk][1],   ah[0], al[0]);
            split2(s[2*kk][2],   s[2*kk][3],   ah[1], al[1]);
            split2(s[2*kk+1][0], s[2*kk+1][1], ah[2], al[2]);
            split2(s[2*kk+1][2], s[2*kk+1][3], ah[3], al[3]);
            #pragma unroll
            for (int d16 = 0; d16 < 4; ++d16) {
                int g = lane >> 3, li = lane & 7;
                int row = kk * 16 + ((g & 1) << 3) + li;
                int c = d16 * 2 + (g >> 1);
                uint32_t so = aswz(row, c);
                uint32_t vh4[4], vl4[4];
                ldsm_x4_t(vh4[0], vh4[1], vh4[2], vh4[3], sb + ATT_VH + so);
                ldsm_x4_t(vl4[0], vl4[1], vl4[2], vl4[3], sb + ATT_VL + so);
                mma2(o[2*d16],   ah, vh4[0], vh4[1]);
                mma2(o[2*d16],   al, vh4[0], vh4[1]);
                mma2(o[2*d16],   ah, vl4[0], vl4[1]);
                mma2(o[2*d16+1], ah, vh4[2], vh4[3]);
                mma2(o[2*d16+1], al, vh4[2], vh4[3]);
                mma2(o[2*d16+1], ah, vl4[2], vl4[3]);
            }
        }
    }

    // ---- epilogue: o/l -> bf16 hi/lo into proj-A buffers ----
    float r0 = 1.f / l0, r1 = 1.f / l1;
    int rg = lane >> 2, t2 = (lane & 3) << 1;
    int row0 = q0 + w * 16 + rg, row1 = row0 + 8;
    #pragma unroll
    for (int nf = 0; nf < 8; ++nf) {
        int col = hh * DH + nf * 8 + t2;
        if (row0 < SEQ) {
            size_t gi = (size_t)(b * SEQ + row0) * CH + col;
            uint32_t hp, lp;
            split2(o[nf][0] * r0, o[nf][1] * r0, hp, lp);
            *(uint32_t*)(g_xh + gi) = hp;
            *(uint32_t*)(g_xl + gi) = lp;
        }
        if (row1 < SEQ) {
            size_t gi = (size_t)(b * SEQ + row1) * CH + col;
            uint32_t hp, lp;
            split2(o[nf][2] * r1, o[nf][3] * r1, hp, lp);
            *(uint32_t*)(g_xh + gi) = hp;
            *(uint32_t*)(g_xl + gi) = lp;
        }
    }
}

// ---------------------------------------------------------------------------
extern "C" void kernel_launch(void* const* d_in, const int* in_sizes, int n_in,
                              void* d_out, int out_size)
{
    const float* x      = (const float*)d_in[0];
    const float* qkv_w  = (const float*)d_in[1];
    const float* qkv_b  = (const float*)d_in[2];
    const float* proj_w = (const float*)d_in[3];
    const float* proj_b = (const float*)d_in[4];
    float* out = (float*)d_out;

    cudaFuncSetAttribute(attn_mma, cudaFuncAttributeMaxDynamicSharedMemorySize, ATT_SMEM);

    split_kernel<<<(MROWS*CH + 255)/256, 256>>>(x, 0, MROWS*CH);
    split_kernel<<<(QKV_N*CH + 255)/256, 256>>>(qkv_w, 1, QKV_N*CH);
    split_kernel<<<(CH*CH + 255)/256, 256>>>(proj_w, 2, CH*CH);

    mma_gemm<0><<<dim3(QKV_N/128, (MROWS + 127)/128), 256>>>(qkv_b, nullptr);

    attn_mma<<<dim3((SEQ + QT - 1)/QT, NH, BN), 256, ATT_SMEM>>>();

    mma_gemm<1><<<dim3(CH/128, (MROWS + 127)/128), 256>>>(proj_b, out);
}